// round 13
// baseline (speedup 1.0000x reference)
#include <cuda_runtime.h>
#include <cuda_bf16.h>
#include <cuda_fp16.h>
#include <mma.h>
#include <cstdint>

using namespace nvcuda;

#define NN 100000
#define EE 1600000
#define FF 64
#define KK 6
#define NBLK_SCAN 98   /* ceil(NN/1024) */

// 2^112 : compensates the <<13 fp16->fp32 bit-trick (exact, power of two)
#define SC112 5.1922968585348276e33f

// ---------------- scratch (static device globals; allocation-free) ----------
__device__ int    g_deg[NN];
__device__ float  g_dinv[NN];
__device__ int    g_cnt[NN];
__device__ int    g_cursor[NN];
__device__ int    g_rowptr[NN + 1];
__device__ int    g_bsum[NBLK_SCAN];
__device__ int    g_boff[NBLK_SCAN];
__device__ int    g_srcs[EE];
__device__ float  g_wts[EE];                   // edge weight PRE-SCALED by 2^112
__device__ __half g_xh[(size_t)NN * FF];       // fp16 copy of x (gather source)
__device__ __half g_tx[5][(size_t)NN * FF];    // Tx1..Tx5 in fp16

// fp16x2 -> 2 raw floats that are (true value) * 2^-112. ALU-pipe only.
__device__ __forceinline__ float2 h2raw(uint32_t r) {
    uint32_t lo = ((r << 16) & 0x80000000u) | ((r << 13) & 0x0FFFE000u);
    uint32_t hi = ( r        & 0x80000000u) | ((r >>  3) & 0x0FFFE000u);
    return make_float2(__uint_as_float(lo), __uint_as_float(hi));
}
// fp16x2 -> 2 true floats (raw * 2^112; FMUL on fma pipe, no F2F)
__device__ __forceinline__ float2 h2f2(uint32_t r) {
    float2 v = h2raw(r);
    v.x *= SC112; v.y *= SC112;
    return v;
}

// ---------------- CSR build (EXACT R1 shape) --------------------------------
__global__ void zero_kernel() {
    int i = blockIdx.x * blockDim.x + threadIdx.x;
    if (i < NN) { g_deg[i] = 0; g_cnt[i] = 0; g_cursor[i] = 0; }
}

__global__ void convx_kernel(const float* __restrict__ x) {
    int i = blockIdx.x * blockDim.x + threadIdx.x;   // over NN*FF/2 pairs
    if (i < NN * FF / 2) {
        float2 v = ((const float2*)x)[i];
        ((__half2*)g_xh)[i] = __floats2half2_rn(v.x, v.y);
    }
}

__global__ void hist_kernel(const int* __restrict__ ei) {
    int e = blockIdx.x * blockDim.x + threadIdx.x;
    if (e < EE) {
        atomicAdd(&g_deg[ei[e]], 1);
        atomicAdd(&g_cnt[ei[EE + e]], 1);
    }
}

__global__ void dinv_kernel() {
    int i = blockIdx.x * blockDim.x + threadIdx.x;
    if (i < NN) {
        int d = g_deg[i];
        g_dinv[i] = (d > 0) ? rsqrtf((float)d) : 0.0f;
    }
}

__global__ void scanA_kernel() {
    __shared__ int sh[1024];
    int t   = threadIdx.x;
    int idx = blockIdx.x * 1024 + t;
    int v   = (idx < NN) ? g_cnt[idx] : 0;
    sh[t] = v;
    __syncthreads();
    for (int off = 1; off < 1024; off <<= 1) {
        int tv = (t >= off) ? sh[t - off] : 0;
        __syncthreads();
        sh[t] += tv;
        __syncthreads();
    }
    if (idx < NN) g_rowptr[idx] = sh[t] - v;
    if (t == 1023) g_bsum[blockIdx.x] = sh[1023];
}

__global__ void scanB_kernel() {
    if (threadIdx.x == 0) {
        int acc = 0;
        for (int i = 0; i < NBLK_SCAN; i++) { g_boff[i] = acc; acc += g_bsum[i]; }
        g_rowptr[NN] = acc;
    }
}

__global__ void scanC_kernel() {
    int idx = blockIdx.x * blockDim.x + threadIdx.x;
    if (idx < NN) g_rowptr[idx] += g_boff[idx >> 10];
}

__global__ void scatter_kernel(const int* __restrict__ ei) {
    int e = blockIdx.x * blockDim.x + threadIdx.x;
    if (e < EE) {
        int r = ei[e];
        int c = ei[EE + e];
        int pos = g_rowptr[c] + atomicAdd(&g_cursor[c], 1);
        g_srcs[pos] = r;
        g_wts[pos]  = -(g_dinv[r] * g_dinv[c]) * SC112;   // fold 2^112 here
    }
}

// ---------------- propagation: Tx_out = alpha*(L_hat @ h) - sub -------------
// One warp per node; lane owns 2 features. fp16 gathers (128B/warp) widened
// via ALU bit-trick; weight carries the 2^112 compensation. No F2F in loop.
__global__ void prop_kernel(int h_idx, int sub_idx, float alpha, int out_idx) {
    int gw   = (blockIdx.x * blockDim.x + threadIdx.x) >> 5;
    int lane = threadIdx.x & 31;
    if (gw >= NN) return;

    const __half* h = (h_idx < 0) ? g_xh : g_tx[h_idx];
    int s = g_rowptr[gw];
    int e = g_rowptr[gw + 1];

    float ax = 0.0f, ay = 0.0f;
    for (int i = s; i < e; i++) {
        int   sr = g_srcs[i];                         // lane-uniform broadcast
        float wv = g_wts[i];                          // = w * 2^112
        uint32_t r = ((const uint32_t*)(h + (size_t)sr * FF))[lane];  // 128B/warp
        float2 hv = h2raw(r);                         // true/2^112 (ALU ops)
        ax = fmaf(wv, hv.x, ax);                      // exact: w*value
        ay = fmaf(wv, hv.y, ay);
    }
    float rx = alpha * ax, ry = alpha * ay;
    if (sub_idx > -2) {
        const __half* sb = (sub_idx < 0) ? g_xh : g_tx[sub_idx];
        float2 sv = h2f2(((const uint32_t*)(sb + (size_t)gw * FF))[lane]);
        rx -= sv.x; ry -= sv.y;
    }
    ((__half2*)(g_tx[out_idx] + (size_t)gw * FF))[lane] = __floats2half2_rn(rx, ry);
}

// ================= wmma bf16 GEMM: out = relu(sum_k Tx_k @ W_k + b) =========
// CTA = 256 threads / 8 warps; tile = 32 nodes x 64 outs (NN = 3125*32 exact).
// 2-term bf16 split (hh + hl + lh). k=0 from fp32 x (exact); k>=1 from fp16 Tx
// widened via the bit-trick (fp16 -> bf16 hi/lo is exact).

#define APAD 72   /* bf16 row stride for A/W smem tiles (bank-conflict pad) */

__device__ __forceinline__ void wm_split(float v, __nv_bfloat16& h, __nv_bfloat16& l) {
    h = __float2bfloat16(v);
    l = __float2bfloat16(v - __bfloat162float(h));
}

__global__ __launch_bounds__(256) void wmma_gemm_kernel(const float* __restrict__ x,
                                                        const float* __restrict__ W,
                                                        const float* __restrict__ b,
                                                        float* __restrict__ out) {
    __shared__ __nv_bfloat16 sAhi[32 * APAD];
    __shared__ __nv_bfloat16 sAlo[32 * APAD];
    __shared__ __nv_bfloat16 sWhi[64 * APAD];
    __shared__ __nv_bfloat16 sWlo[64 * APAD];
    __shared__ float         sOut[32 * 64];

    int tid  = threadIdx.x;
    int warp = tid >> 5;
    int m0   = blockIdx.x * 32;

    int w_m = (warp >> 2) * 16;     // 0 or 16: node-subtile row
    int w_n = (warp & 3) * 16;      // 0,16,32,48: out-feature subtile col

    wmma::fragment<wmma::accumulator, 16, 16, 16, float> acc;
    wmma::fill_fragment(acc, 0.0f);

#pragma unroll 1
    for (int k = 0; k < KK; k++) {
        // ---- stage A tile: 32 nodes x 64 features -> bf16 hi/lo ----
        if (k == 0) {                      // from x (fp32)
            for (int idx = tid; idx < 32 * 16; idx += 256) {
                int r = idx >> 4, c4 = idx & 15;
                float4 v = __ldg((const float4*)(x + (size_t)(m0 + r) * FF) + c4);
                __nv_bfloat16 h0, l0, h1, l1, h2, l2, h3, l3;
                wm_split(v.x, h0, l0); wm_split(v.y, h1, l1);
                wm_split(v.z, h2, l2); wm_split(v.w, h3, l3);
                int o = r * APAD + c4 * 4;
                sAhi[o] = h0; sAhi[o+1] = h1; sAhi[o+2] = h2; sAhi[o+3] = h3;
                sAlo[o] = l0; sAlo[o+1] = l1; sAlo[o+2] = l2; sAlo[o+3] = l3;
            }
        } else {                           // from Tx_{k} (fp16), bit-trick widen
            const __half* hb = g_tx[k - 1];
            int r  = tid >> 3;             // 32 rows
            int c8 = tid & 7;              // 8 chunks of 8 halves
            const uint32_t* src = (const uint32_t*)(hb + (size_t)(m0 + r) * FF + c8 * 8);
            int o = r * APAD + c8 * 8;
#pragma unroll
            for (int j = 0; j < 4; j++) {
                float2 v = h2f2(__ldg(src + j));
                __nv_bfloat16 h0, l0, h1, l1;
                wm_split(v.x, h0, l0); wm_split(v.y, h1, l1);
                sAhi[o + 2*j] = h0; sAhi[o + 2*j + 1] = h1;
                sAlo[o + 2*j] = l0; sAlo[o + 2*j + 1] = l1;
            }
        }
        // ---- stage W_k: 64x64 row-major (in x out) -> bf16 hi/lo ----
        for (int idx = tid; idx < 64 * 16; idx += 256) {
            int r = idx >> 4, c4 = idx & 15;
            float4 v = __ldg((const float4*)(W + k * FF * FF + r * FF) + c4);
            __nv_bfloat16 h0, l0, h1, l1, h2, l2, h3, l3;
            wm_split(v.x, h0, l0); wm_split(v.y, h1, l1);
            wm_split(v.z, h2, l2); wm_split(v.w, h3, l3);
            int o = r * APAD + c4 * 4;
            sWhi[o] = h0; sWhi[o+1] = h1; sWhi[o+2] = h2; sWhi[o+3] = h3;
            sWlo[o] = l0; sWlo[o+1] = l1; sWlo[o+2] = l2; sWlo[o+3] = l3;
        }
        __syncthreads();

        // ---- 4 k-chunks x 3 split products ----
#pragma unroll
        for (int kk = 0; kk < 4; kk++) {
            wmma::fragment<wmma::matrix_a, 16, 16, 16, __nv_bfloat16, wmma::row_major> a_hi, a_lo;
            wmma::fragment<wmma::matrix_b, 16, 16, 16, __nv_bfloat16, wmma::row_major> b_hi, b_lo;
            wmma::load_matrix_sync(a_hi, &sAhi[w_m * APAD + kk * 16], APAD);
            wmma::load_matrix_sync(a_lo, &sAlo[w_m * APAD + kk * 16], APAD);
            wmma::load_matrix_sync(b_hi, &sWhi[(kk * 16) * APAD + w_n], APAD);
            wmma::load_matrix_sync(b_lo, &sWlo[(kk * 16) * APAD + w_n], APAD);
            wmma::mma_sync(acc, a_hi, b_hi, acc);
            wmma::mma_sync(acc, a_hi, b_lo, acc);
            wmma::mma_sync(acc, a_lo, b_hi, acc);
        }
        __syncthreads();   // before restaging smem for next k
    }

    // ---- epilogue: frag -> smem, bias + relu, float4 stores ----
    wmma::store_matrix_sync(&sOut[w_m * 64 + w_n], acc, 64, wmma::mem_row_major);
    __syncthreads();

    for (int idx = tid; idx < 32 * 16; idx += 256) {
        int r = idx >> 4, c4 = idx & 15;
        float4 v = ((const float4*)(sOut + r * 64))[c4];
        v.x = fmaxf(v.x + __ldg(b + c4 * 4 + 0), 0.0f);
        v.y = fmaxf(v.y + __ldg(b + c4 * 4 + 1), 0.0f);
        v.z = fmaxf(v.z + __ldg(b + c4 * 4 + 2), 0.0f);
        v.w = fmaxf(v.w + __ldg(b + c4 * 4 + 3), 0.0f);
        ((float4*)(out + (size_t)(m0 + r) * FF))[c4] = v;
    }
}

// ---------------- launch ----------------------------------------------------
extern "C" void kernel_launch(void* const* d_in, const int* in_sizes, int n_in,
                              void* d_out, int out_size) {
    const float* x  = (const float*)d_in[0];   // [N, 64]
    const int*   ei = (const int*)d_in[1];     // [2, E]: src row then dst row
    const float* W  = (const float*)d_in[2];   // [6, 64, 64]
    const float* b  = (const float*)d_in[3];   // [64]
    float* out = (float*)d_out;                // [N, 64]

    const int TB = 256;
    zero_kernel   <<<(NN + TB - 1) / TB, TB>>>();
    convx_kernel  <<<(NN * FF / 2 + TB - 1) / TB, TB>>>(x);
    hist_kernel   <<<(EE + TB - 1) / TB, TB>>>(ei);
    dinv_kernel   <<<(NN + TB - 1) / TB, TB>>>();
    scanA_kernel  <<<NBLK_SCAN, 1024>>>();
    scanB_kernel  <<<1, 32>>>();
    scanC_kernel  <<<(NN + TB - 1) / TB, TB>>>();
    scatter_kernel<<<(EE + TB - 1) / TB, TB>>>(ei);

    int prop_blocks = (NN * 32 + TB - 1) / TB;   // warp per node
    prop_kernel<<<prop_blocks, TB>>>(-1, -2, 1.0f, 0);  // Tx1 = L x
    prop_kernel<<<prop_blocks, TB>>>( 0, -1, 2.0f, 1);  // Tx2 = 2 L Tx1 - x
    prop_kernel<<<prop_blocks, TB>>>( 1,  0, 2.0f, 2);  // Tx3
    prop_kernel<<<prop_blocks, TB>>>( 2,  1, 2.0f, 3);  // Tx4
    prop_kernel<<<prop_blocks, TB>>>( 3,  2, 2.0f, 4);  // Tx5

    wmma_gemm_kernel<<<NN / 32, TB>>>(x, W, b, out);   // 3125 CTAs, exact
}

// round 14
// speedup vs baseline: 1.5371x; 1.5371x over previous
#include <cuda_runtime.h>
#include <cuda_bf16.h>
#include <mma.h>
#include <cstdint>

using namespace nvcuda;

#define NN 100000
#define EE 1600000
#define FF 64
#define KK 6
#define NBLK_SCAN 98   /* ceil(NN/1024) */

// ---------------- scratch (static device globals; allocation-free) ----------
__device__ int   g_deg[NN];
__device__ float g_dinv[NN];
__device__ int   g_cnt[NN];
__device__ int   g_cursor[NN];
__device__ int   g_rowptr[NN + 1];
__device__ int   g_bsum[NBLK_SCAN];
__device__ int   g_boff[NBLK_SCAN];
__device__ int   g_srcs[EE];
__device__ float g_wts[EE];
__device__ float g_tx[5][(size_t)NN * FF];   // Tx1..Tx5 (fp32 — fp16 is banned here)

// ---------------- CSR build (EXACT R1/R11) -----------------------------------
__global__ void zero_kernel() {
    int i = blockIdx.x * blockDim.x + threadIdx.x;
    if (i < NN) { g_deg[i] = 0; g_cnt[i] = 0; g_cursor[i] = 0; }
}

__global__ void hist_kernel(const int* __restrict__ ei) {
    int e = blockIdx.x * blockDim.x + threadIdx.x;
    if (e < EE) {
        atomicAdd(&g_deg[ei[e]], 1);
        atomicAdd(&g_cnt[ei[EE + e]], 1);
    }
}

__global__ void dinv_kernel() {
    int i = blockIdx.x * blockDim.x + threadIdx.x;
    if (i < NN) {
        int d = g_deg[i];
        g_dinv[i] = (d > 0) ? rsqrtf((float)d) : 0.0f;
    }
}

__global__ void scanA_kernel() {
    __shared__ int sh[1024];
    int t   = threadIdx.x;
    int idx = blockIdx.x * 1024 + t;
    int v   = (idx < NN) ? g_cnt[idx] : 0;
    sh[t] = v;
    __syncthreads();
    for (int off = 1; off < 1024; off <<= 1) {
        int tv = (t >= off) ? sh[t - off] : 0;
        __syncthreads();
        sh[t] += tv;
        __syncthreads();
    }
    if (idx < NN) g_rowptr[idx] = sh[t] - v;
    if (t == 1023) g_bsum[blockIdx.x] = sh[1023];
}

__global__ void scanB_kernel() {
    if (threadIdx.x == 0) {
        int acc = 0;
        for (int i = 0; i < NBLK_SCAN; i++) { g_boff[i] = acc; acc += g_bsum[i]; }
        g_rowptr[NN] = acc;
    }
}

__global__ void scanC_kernel() {
    int idx = blockIdx.x * blockDim.x + threadIdx.x;
    if (idx < NN) g_rowptr[idx] += g_boff[idx >> 10];
}

__global__ void scatter_kernel(const int* __restrict__ ei) {
    int e = blockIdx.x * blockDim.x + threadIdx.x;
    if (e < EE) {
        int r = ei[e];
        int c = ei[EE + e];
        int pos = g_rowptr[c] + atomicAdd(&g_cursor[c], 1);
        g_srcs[pos] = r;
        g_wts[pos]  = -(g_dinv[r] * g_dinv[c]);
    }
}

// ---------------- propagation: Tx_out = alpha*(L_hat @ h) - sub -------------
// One warp per destination node; lane owns 2 features (float2).
// ONLY change vs R11: 4-wide software pipeline — 4 independent edge loads,
// then 4 independent gathers in flight. Separate srcs/wts arrays (int2 banned).
// FMA accumulation order per edge is identical to R11 (e0,e1,e2,e3 serial).
__global__ void prop_kernel(const float* __restrict__ x,
                            int h_idx, int sub_idx, float alpha, int out_idx) {
    int gw   = (blockIdx.x * blockDim.x + threadIdx.x) >> 5;
    int lane = threadIdx.x & 31;
    if (gw >= NN) return;

    const float* h = (h_idx < 0) ? x : g_tx[h_idx];
    int s = g_rowptr[gw];
    int e = g_rowptr[gw + 1];

    float ax = 0.0f, ay = 0.0f;
    int i = s;
    for (; i + 4 <= e; i += 4) {
        int s0 = g_srcs[i];     int s1 = g_srcs[i + 1];
        int s2 = g_srcs[i + 2]; int s3 = g_srcs[i + 3];
        float w0 = g_wts[i];     float w1 = g_wts[i + 1];
        float w2 = g_wts[i + 2]; float w3 = g_wts[i + 3];
        float2 h0 = ((const float2*)(h + (size_t)s0 * FF))[lane];
        float2 h1 = ((const float2*)(h + (size_t)s1 * FF))[lane];
        float2 h2 = ((const float2*)(h + (size_t)s2 * FF))[lane];
        float2 h3 = ((const float2*)(h + (size_t)s3 * FF))[lane];
        ax = fmaf(w0, h0.x, ax); ay = fmaf(w0, h0.y, ay);
        ax = fmaf(w1, h1.x, ax); ay = fmaf(w1, h1.y, ay);
        ax = fmaf(w2, h2.x, ax); ay = fmaf(w2, h2.y, ay);
        ax = fmaf(w3, h3.x, ax); ay = fmaf(w3, h3.y, ay);
    }
    for (; i < e; i++) {
        int   sr = g_srcs[i];
        float wv = g_wts[i];
        float2 hv = ((const float2*)(h + (size_t)sr * FF))[lane];
        ax = fmaf(wv, hv.x, ax);
        ay = fmaf(wv, hv.y, ay);
    }

    float rx = alpha * ax, ry = alpha * ay;
    if (sub_idx > -2) {
        const float* sb = (sub_idx < 0) ? x : g_tx[sub_idx];
        float2 sv = ((const float2*)(sb + (size_t)gw * FF))[lane];
        rx -= sv.x; ry -= sv.y;
    }
    float2 r; r.x = rx; r.y = ry;
    ((float2*)(g_tx[out_idx] + (size_t)gw * FF))[lane] = r;
}

// ================= wmma bf16 GEMM (EXACT R11) ===============================
// CTA = 256 threads / 8 warps; tile = 32 nodes x 64 outs (NN = 3125*32 exact).
// 2-term bf16 split (hh + hl + lh) for fp32-class accuracy on the HMMA pipe.

#define APAD 72   /* bf16 row stride for A/W smem tiles (bank-conflict pad) */

__device__ __forceinline__ void wm_split(float v, __nv_bfloat16& h, __nv_bfloat16& l) {
    h = __float2bfloat16(v);
    l = __float2bfloat16(v - __bfloat162float(h));
}

__global__ __launch_bounds__(256) void wmma_gemm_kernel(const float* __restrict__ x,
                                                        const float* __restrict__ W,
                                                        const float* __restrict__ b,
                                                        float* __restrict__ out) {
    __shared__ __nv_bfloat16 sAhi[32 * APAD];
    __shared__ __nv_bfloat16 sAlo[32 * APAD];
    __shared__ __nv_bfloat16 sWhi[64 * APAD];
    __shared__ __nv_bfloat16 sWlo[64 * APAD];
    __shared__ float         sOut[32 * 64];

    int tid  = threadIdx.x;
    int warp = tid >> 5;
    int m0   = blockIdx.x * 32;

    int w_m = (warp >> 2) * 16;     // 0 or 16: node-subtile row
    int w_n = (warp & 3) * 16;      // 0,16,32,48: out-feature subtile col

    wmma::fragment<wmma::accumulator, 16, 16, 16, float> acc;
    wmma::fill_fragment(acc, 0.0f);

#pragma unroll 1
    for (int k = 0; k < KK; k++) {
        // ---- stage A tile: 32 nodes x 64 features, fp32 -> bf16 hi/lo ----
        const float* hb = (k == 0) ? x : g_tx[k - 1];
        for (int idx = tid; idx < 32 * 16; idx += 256) {
            int r = idx >> 4, c4 = idx & 15;
            float4 v = __ldg((const float4*)(hb + (size_t)(m0 + r) * FF) + c4);
            __nv_bfloat16 h0, l0, h1, l1, h2, l2, h3, l3;
            wm_split(v.x, h0, l0); wm_split(v.y, h1, l1);
            wm_split(v.z, h2, l2); wm_split(v.w, h3, l3);
            int o = r * APAD + c4 * 4;
            sAhi[o] = h0; sAhi[o+1] = h1; sAhi[o+2] = h2; sAhi[o+3] = h3;
            sAlo[o] = l0; sAlo[o+1] = l1; sAlo[o+2] = l2; sAlo[o+3] = l3;
        }
        // ---- stage W_k: 64x64 row-major (in x out) -> bf16 hi/lo ----
        for (int idx = tid; idx < 64 * 16; idx += 256) {
            int r = idx >> 4, c4 = idx & 15;
            float4 v = __ldg((const float4*)(W + k * FF * FF + r * FF) + c4);
            __nv_bfloat16 h0, l0, h1, l1, h2, l2, h3, l3;
            wm_split(v.x, h0, l0); wm_split(v.y, h1, l1);
            wm_split(v.z, h2, l2); wm_split(v.w, h3, l3);
            int o = r * APAD + c4 * 4;
            sWhi[o] = h0; sWhi[o+1] = h1; sWhi[o+2] = h2; sWhi[o+3] = h3;
            sWlo[o] = l0; sWlo[o+1] = l1; sWlo[o+2] = l2; sWlo[o+3] = l3;
        }
        __syncthreads();

        // ---- 4 k-chunks x 3 split products ----
#pragma unroll
        for (int kk = 0; kk < 4; kk++) {
            wmma::fragment<wmma::matrix_a, 16, 16, 16, __nv_bfloat16, wmma::row_major> a_hi, a_lo;
            wmma::fragment<wmma::matrix_b, 16, 16, 16, __nv_bfloat16, wmma::row_major> b_hi, b_lo;
            wmma::load_matrix_sync(a_hi, &sAhi[w_m * APAD + kk * 16], APAD);
            wmma::load_matrix_sync(a_lo, &sAlo[w_m * APAD + kk * 16], APAD);
            wmma::load_matrix_sync(b_hi, &sWhi[(kk * 16) * APAD + w_n], APAD);
            wmma::load_matrix_sync(b_lo, &sWlo[(kk * 16) * APAD + w_n], APAD);
            wmma::mma_sync(acc, a_hi, b_hi, acc);
            wmma::mma_sync(acc, a_hi, b_lo, acc);
            wmma::mma_sync(acc, a_lo, b_hi, acc);
        }
        __syncthreads();   // before restaging smem for next k
    }

    // ---- epilogue: frag -> smem, bias + relu, float4 stores ----
    wmma::store_matrix_sync(&sOut[w_m * 64 + w_n], acc, 64, wmma::mem_row_major);
    __syncthreads();

    for (int idx = tid; idx < 32 * 16; idx += 256) {
        int r = idx >> 4, c4 = idx & 15;
        float4 v = ((const float4*)(sOut + r * 64))[c4];
        v.x = fmaxf(v.x + __ldg(b + c4 * 4 + 0), 0.0f);
        v.y = fmaxf(v.y + __ldg(b + c4 * 4 + 1), 0.0f);
        v.z = fmaxf(v.z + __ldg(b + c4 * 4 + 2), 0.0f);
        v.w = fmaxf(v.w + __ldg(b + c4 * 4 + 3), 0.0f);
        ((float4*)(out + (size_t)(m0 + r) * FF))[c4] = v;
    }
}

// ---------------- launch ----------------------------------------------------
extern "C" void kernel_launch(void* const* d_in, const int* in_sizes, int n_in,
                              void* d_out, int out_size) {
    const float* x  = (const float*)d_in[0];   // [N, 64]
    const int*   ei = (const int*)d_in[1];     // [2, E]: src row then dst row
    const float* W  = (const float*)d_in[2];   // [6, 64, 64]
    const float* b  = (const float*)d_in[3];   // [64]
    float* out = (float*)d_out;                // [N, 64]

    const int TB = 256;
    zero_kernel   <<<(NN + TB - 1) / TB, TB>>>();
    hist_kernel   <<<(EE + TB - 1) / TB, TB>>>(ei);
    dinv_kernel   <<<(NN + TB - 1) / TB, TB>>>();
    scanA_kernel  <<<NBLK_SCAN, 1024>>>();
    scanB_kernel  <<<1, 32>>>();
    scanC_kernel  <<<(NN + TB - 1) / TB, TB>>>();
    scatter_kernel<<<(EE + TB - 1) / TB, TB>>>(ei);

    int prop_blocks = (NN * 32 + TB - 1) / TB;   // warp per node
    prop_kernel<<<prop_blocks, TB>>>(x, -1, -2, 1.0f, 0);  // Tx1 = L x
    prop_kernel<<<prop_blocks, TB>>>(x,  0, -1, 2.0f, 1);  // Tx2 = 2 L Tx1 - x
    prop_kernel<<<prop_blocks, TB>>>(x,  1,  0, 2.0f, 2);  // Tx3
    prop_kernel<<<prop_blocks, TB>>>(x,  2,  1, 2.0f, 3);  // Tx4
    prop_kernel<<<prop_blocks, TB>>>(x,  3,  2, 2.0f, 4);  // Tx5

    wmma_gemm_kernel<<<NN / 32, TB>>>(x, W, b, out);   // 3125 CTAs, exact
}